// round 12
// baseline (speedup 1.0000x reference)
#include <cuda_runtime.h>
#include <cuda_fp16.h>
#include <cstdint>

// ---------------- problem constants ----------------
#define HW_      65536
#define CDIM     64
#define NKP      400        // = 25 frags x 16, exact
#define PMAX     2
#define NSTRIP   74         // x P=2 -> 148 CTAs = one full wave (required: <= #SMs)
#define NCH128   512        // 65536 / 128
#define CHUNK_M  128        // two 64-col halves per barrier window
#define NTHREADS 512        // 16 warps
#define LOGIT_C  144.26950408889634f   // 100 * log2(e)

// smem: A rows 144B stride (128B fp16 data + 16B pad); B bufs 128 rows x 144B
#define SA     0
#define SB     57600        // 2 bufs x 18432
#define SMEMSZ 94464

// ---------------- device scratch ----------------
__device__ float4   g_part4[PMAX * NKP * NSTRIP]; // (S, X, Y, _) per kp per strip
__device__ unsigned g_ctr = 0;                    // last-arriver counter (self-resetting)

// ---------------- helpers ----------------
__device__ __forceinline__ float ex2f(float x) {
    float y; asm("ex2.approx.ftz.f32 %0, %1;" : "=f"(y) : "f"(x)); return y;
}
__device__ __forceinline__ uint32_t pkh2(float a, float b) {
    __half2 h = __floats2half2_rn(a, b);
    return *reinterpret_cast<uint32_t*>(&h);
}
__device__ __forceinline__ void ldsm4(uint32_t& r0, uint32_t& r1, uint32_t& r2, uint32_t& r3,
                                      uint32_t addr) {
    asm volatile("ldmatrix.sync.aligned.m8n8.x4.shared.b16 {%0,%1,%2,%3}, [%4];"
                 : "=r"(r0), "=r"(r1), "=r"(r2), "=r"(r3) : "r"(addr));
}
__device__ __forceinline__ void mma16816(float* c, const uint32_t* a, uint32_t b0, uint32_t b1) {
    asm volatile(
        "mma.sync.aligned.m16n8k16.row.col.f32.f16.f16.f32 "
        "{%0,%1,%2,%3}, {%4,%5,%6,%7}, {%8,%9}, {%0,%1,%2,%3};"
        : "+f"(c[0]), "+f"(c[1]), "+f"(c[2]), "+f"(c[3])
        : "r"(a[0]), "r"(a[1]), "r"(a[2]), "r"(a[3]), "r"(b0), "r"(b1));
}

// ---------------- kernel: fp16 mma GEMM + fused softmax moments + fused combine ----------------
// grid (NSTRIP, P), 512 threads / 16 warps.
// Frags of 16 kp: warp w owns frag w; warps 8-15 also frag w+8; warp 0 also frag 24.
// Staging: all 512 threads; thread owns (col, k-quarter): col = (w&7)*8+(lane&7)+(w>=8)*64,
// kg = lane>>3; column norms via intra-warp shfl (dense read exactly once).
// One __syncthreads per 128-col chunk. Last-arriving CTA combines all partials.
__global__ void __launch_bounds__(NTHREADS, 1)
k_match(const float* __restrict__ dense, const float* __restrict__ kdesc,
        const float* __restrict__ kscores,
        const int* __restrict__ tgt_ids, const int* __restrict__ src_ids,
        float* __restrict__ out, int P, int out_size) {
    extern __shared__ char sm[];
    const uint32_t sb = (uint32_t)__cvta_generic_to_shared(sm);
    const int tid = threadIdx.x, w = tid >> 5, lane = tid & 31;
    const int strip = blockIdx.x, p = blockIdx.y;
    const int c0 = (strip * NCH128) / NSTRIP;
    const int c1 = ((strip + 1) * NCH128) / NSTRIP;
    const float* srcb = dense + (size_t)src_ids[p] * CDIM * HW_;

    const int mcol = (w & 7) * 8 + (lane & 7) + ((w >= 8) ? 64 : 0);  // col in 128-chunk
    const int kg   = lane >> 3;                                       // k-quarter

    // ---- early LDG of chunk c0 ----
    float R[16];
#pragma unroll
    for (int i = 0; i < 16; ++i)
        R[i] = srcb[(size_t)(kg * 16 + i) * HW_ + (size_t)c0 * CHUNK_M + mcol];

    // ---- build A tile: normalize tgt inline, fold LOGIT_C, single fp16 ----
    if (tid < NKP) {
        const int kp = tid;
        const float* tb = kdesc + (size_t)tgt_ids[p] * CDIM * NKP + kp;
        float v[CDIM];
        float ss = 0.f;
#pragma unroll
        for (int c = 0; c < CDIM; ++c) { v[c] = tb[c * NKP]; ss = fmaf(v[c], v[c], ss); }
        float inv = LOGIT_C / fmaxf(sqrtf(ss), 1e-12f);
#pragma unroll
        for (int kb = 0; kb < CDIM; kb += 8) {
            uint32_t q[4];
#pragma unroll
            for (int j = 0; j < 4; ++j)
                q[j] = pkh2(v[kb + 2 * j] * inv, v[kb + 2 * j + 1] * inv);
            *(uint4*)(sm + SA + kp * 144 + kb * 2) = make_uint4(q[0], q[1], q[2], q[3]);
        }
    }

    // ---- prologue: convert chunk c0 (norm via shfl), prefetch c0+1 ----
    {
        float ss = 0.f;
#pragma unroll
        for (int i = 0; i < 16; ++i) ss = fmaf(R[i], R[i], ss);
        ss += __shfl_xor_sync(0xffffffffu, ss, 8);
        ss += __shfl_xor_sync(0xffffffffu, ss, 16);
        float inv = 1.0f / fmaxf(sqrtf(ss), 1e-12f);
        char* bb = sm + SB + (c0 & 1) * 18432;
        uint32_t q[8];
#pragma unroll
        for (int j = 0; j < 8; ++j) q[j] = pkh2(R[2 * j] * inv, R[2 * j + 1] * inv);
        *(uint4*)(bb + mcol * 144 + kg * 32)      = make_uint4(q[0], q[1], q[2], q[3]);
        *(uint4*)(bb + mcol * 144 + kg * 32 + 16) = make_uint4(q[4], q[5], q[6], q[7]);
        if (c0 + 1 < c1) {
#pragma unroll
            for (int i = 0; i < 16; ++i)
                R[i] = srcb[(size_t)(kg * 16 + i) * HW_ + (size_t)(c0 + 1) * CHUNK_M + mcol];
        }
    }

    // frag assignment: slot 0 = frag w; slot 1 = w+8 (warps 8-15) or 24 (warp 0)
    const int f1 = (w >= 8) ? (w + 8) : (w == 0 ? 24 : -1);

    // persistent softmax moment accumulators [slot][rowpart]
    float S[2][2]  = {{0.f,0.f},{0.f,0.f}};
    float XO[2][2] = {{0.f,0.f},{0.f,0.f}};
    float XB[2][2] = {{0.f,0.f},{0.f,0.f}};
    float Yc[2][2] = {{0.f,0.f},{0.f,0.f}};

    const int preA = ((lane & 7) + ((lane >> 3) & 1) * 8) * 144 + ((lane >> 4) & 1) * 16;
    const int preB = ((lane & 7) + ((lane >> 4) & 1) * 8) * 144 + ((lane >> 3) & 1) * 16;
    const float xol = (float)((lane & 3) * 2);

    for (int t = c0; t < c1; ++t) {
        __syncthreads();   // buf[t&1] ready; prior readers of buf[(t+1)&1] done

        // ---- staging first: convert chunk t+1 into buf[(t+1)&1], prefetch t+2 ----
        if (t + 1 < c1) {
            float ss = 0.f;
#pragma unroll
            for (int i = 0; i < 16; ++i) ss = fmaf(R[i], R[i], ss);
            ss += __shfl_xor_sync(0xffffffffu, ss, 8);
            ss += __shfl_xor_sync(0xffffffffu, ss, 16);
            float inv = 1.0f / fmaxf(sqrtf(ss), 1e-12f);
            char* bb = sm + SB + ((t + 1) & 1) * 18432;
            uint32_t q[8];
#pragma unroll
            for (int j = 0; j < 8; ++j) q[j] = pkh2(R[2 * j] * inv, R[2 * j + 1] * inv);
            *(uint4*)(bb + mcol * 144 + kg * 32)      = make_uint4(q[0], q[1], q[2], q[3]);
            *(uint4*)(bb + mcol * 144 + kg * 32 + 16) = make_uint4(q[4], q[5], q[6], q[7]);
            if (t + 2 < c1) {
#pragma unroll
                for (int i = 0; i < 16; ++i)
                    R[i] = srcb[(size_t)(kg * 16 + i) * HW_ + (size_t)(t + 2) * CHUNK_M + mcol];
            }
        }

        // ---- compute chunk t: two 64-col halves ----
#pragma unroll
        for (int half = 0; half < 2; ++half) {
            const uint32_t Bb = sb + SB + (t & 1) * 18432 + half * 9216;
            const int m0h = t * CHUNK_M + half * 64;
            const float xb = (float)(m0h & 255), yv = (float)(m0h >> 8);

#pragma unroll
            for (int slot = 0; slot < 2; ++slot) {
                const int f = (slot == 0) ? w : f1;
                if (f < 0) continue;
                const uint32_t Ah = sb + SA + f * 16 * 144 + preA;
                float c[8][4];
#pragma unroll
                for (int ff = 0; ff < 8; ++ff)   // fold -100*log2e into accumulator init
                    c[ff][0] = c[ff][1] = c[ff][2] = c[ff][3] = -LOGIT_C;

#pragma unroll
                for (int ks = 0; ks < 4; ++ks) {
                    uint32_t ah[4];
                    ldsm4(ah[0], ah[1], ah[2], ah[3], Ah + ks * 32);
#pragma unroll
                    for (int fp = 0; fp < 4; ++fp) {
                        uint32_t b0, b1, b2, b3;
                        ldsm4(b0, b1, b2, b3, Bb + fp * 2304 + preB + ks * 32);
                        mma16816(c[2 * fp],     ah, b0, b1);
                        mma16816(c[2 * fp + 1], ah, b2, b3);
                    }
                }

                // ---- epilogue: w = 2^c; rows = keypoints (in-register moments) ----
                float s0 = S[slot][0], s1 = S[slot][1];
                float x0 = XO[slot][0], x1 = XO[slot][1];
                const float sn0 = s0, sn1 = s1;
#pragma unroll
                for (int ff = 0; ff < 8; ++ff) {
                    float xo = xol + (float)(ff * 8);
                    float w0 = ex2f(c[ff][0]);
                    float w1 = ex2f(c[ff][1]);
                    float w2 = ex2f(c[ff][2]);
                    float w3 = ex2f(c[ff][3]);
                    s0 += w0 + w1;
                    x0 = fmaf(w0, xo, x0); x0 = fmaf(w1, xo + 1.f, x0);
                    s1 += w2 + w3;
                    x1 = fmaf(w2, xo, x1); x1 = fmaf(w3, xo + 1.f, x1);
                }
                S[slot][0] = s0; S[slot][1] = s1; XO[slot][0] = x0; XO[slot][1] = x1;
                XB[slot][0] = fmaf(xb, s0 - sn0, XB[slot][0]);
                XB[slot][1] = fmaf(xb, s1 - sn1, XB[slot][1]);
                Yc[slot][0] = fmaf(yv, s0 - sn0, Yc[slot][0]);
                Yc[slot][1] = fmaf(yv, s1 - sn1, Yc[slot][1]);
            }
        }
    }

    // ---- reduce over the 4 col-lanes and store partials ----
#pragma unroll
    for (int slot = 0; slot < 2; ++slot) {
        const int f = (slot == 0) ? w : f1;
        if (f < 0) continue;
#pragma unroll
        for (int rp = 0; rp < 2; ++rp) {
            float s = S[slot][rp], x = XO[slot][rp] + XB[slot][rp], y = Yc[slot][rp];
            s += __shfl_xor_sync(0xffffffffu, s, 1);
            x += __shfl_xor_sync(0xffffffffu, x, 1);
            y += __shfl_xor_sync(0xffffffffu, y, 1);
            s += __shfl_xor_sync(0xffffffffu, s, 2);
            x += __shfl_xor_sync(0xffffffffu, x, 2);
            y += __shfl_xor_sync(0xffffffffu, y, 2);
            if ((lane & 3) == 0) {
                int kp = f * 16 + (lane >> 2) + 8 * rp;
                g_part4[((size_t)p * NKP + kp) * NSTRIP + strip] = make_float4(s, x, y, 0.f);
            }
        }
    }

    // ---- last-arriver combine (deterministic: one CTA, fixed code order) ----
    __threadfence();
    __shared__ unsigned is_last;
    __syncthreads();
    if (tid == 0) {
        unsigned total = (unsigned)(NSTRIP * P);
        unsigned old = atomicAdd(&g_ctr, 1u);
        is_last = (old == total - 1u) ? 1u : 0u;
    }
    __syncthreads();
    if (is_last) {
        __threadfence();   // acquire: all partial writes visible
        if (tid == 0) {
            int base = P * NKP * 3;
            for (int pp = 0; pp < P; ++pp) {
                if (base + pp < out_size)     out[base + pp]     = (float)tgt_ids[pp];
                if (base + P + pp < out_size) out[base + P + pp] = (float)src_ids[pp];
            }
        }
        for (int g = w; g < P * NKP; g += 16) {
            int pp = g / NKP, kp = g - pp * NKP;
            const float4* bp = &g_part4[((size_t)pp * NKP + kp) * NSTRIP];
            float4 v0 = bp[lane];
            float4 v1 = bp[lane + 32];
            float4 v2 = (lane + 64 < NSTRIP) ? bp[lane + 64] : make_float4(0.f, 0.f, 0.f, 0.f);
            float Sg = v0.x + v1.x + v2.x;
            float Xg = v0.y + v1.y + v2.y;
            float Yg = v0.z + v1.z + v2.z;
#pragma unroll
            for (int off = 16; off; off >>= 1) {
                Sg += __shfl_xor_sync(0xffffffffu, Sg, off);
                Xg += __shfl_xor_sync(0xffffffffu, Xg, off);
                Yg += __shfl_xor_sync(0xffffffffu, Yg, off);
            }
            if (lane == 0) {
                if (g * 2 + 1 < out_size) {
                    out[g * 2 + 0] = Xg / Sg;
                    out[g * 2 + 1] = Yg / Sg;
                }
                int so = P * NKP * 2 + pp * NKP + kp;
                if (so < out_size) out[so] = kscores[tgt_ids[pp] * NKP + kp];
            }
        }
        __syncthreads();
        if (tid == 0) atomicExch(&g_ctr, 0u);   // reset for next graph replay
    }
}

// ---------------- launch ----------------
extern "C" void kernel_launch(void* const* d_in, const int* in_sizes, int n_in,
                              void* d_out, int out_size) {
    const float* kscores = (const float*)d_in[0];
    const float* kdesc   = (const float*)d_in[1];
    const float* dense   = (const float*)d_in[2];
    const int*   tgt_ids = (const int*)d_in[3];
    const int*   src_ids = (const int*)d_in[4];
    int P = in_sizes[3];
    if (P > PMAX) P = PMAX;
    float* out = (float*)d_out;

    cudaFuncSetAttribute(k_match, cudaFuncAttributeMaxDynamicSharedMemorySize, SMEMSZ);
    k_match<<<dim3(NSTRIP, P), NTHREADS, SMEMSZ>>>(dense, kdesc, kscores,
                                                   tgt_ids, src_ids, out, P, out_size);
}

// round 14
// speedup vs baseline: 1.4281x; 1.4281x over previous
#include <cuda_runtime.h>
#include <cuda_fp16.h>
#include <cstdint>

// ---------------- problem constants ----------------
#define HW_      65536
#define CDIM     64
#define NKP      400        // = 25 frags x 16, exact
#define PMAX     2
#define NSTRIP   74         // x P=2 -> 148 CTAs = one full wave
#define NCHUNK_G 1024       // 65536 / 64
#define CHUNK_M  64
#define NTHREADS 512        // 16 warps
#define LOGIT_C  144.26950408889634f   // 100 * log2(e)

// smem: A rows 144B stride (128B fp16 data + 16B pad); B bufs 64 rows x 144B
#define SA     0
#define SB     57600        // 2 bufs x 9216
#define SMEMSZ 76032

// ---------------- device scratch ----------------
// strip-major partials: [strip][p*NKP + kp] -> coalesced combine reads
__device__ float4   g_part4[NSTRIP * PMAX * NKP];
__device__ unsigned g_ctr = 0;                    // last-arriver counter (self-resetting)

// ---------------- helpers ----------------
__device__ __forceinline__ float ex2f(float x) {
    float y; asm("ex2.approx.ftz.f32 %0, %1;" : "=f"(y) : "f"(x)); return y;
}
__device__ __forceinline__ uint32_t pkh2(float a, float b) {
    __half2 h = __floats2half2_rn(a, b);
    return *reinterpret_cast<uint32_t*>(&h);
}
__device__ __forceinline__ void ldsm4(uint32_t& r0, uint32_t& r1, uint32_t& r2, uint32_t& r3,
                                      uint32_t addr) {
    asm volatile("ldmatrix.sync.aligned.m8n8.x4.shared.b16 {%0,%1,%2,%3}, [%4];"
                 : "=r"(r0), "=r"(r1), "=r"(r2), "=r"(r3) : "r"(addr));
}
__device__ __forceinline__ void mma16816(float* c, const uint32_t* a, uint32_t b0, uint32_t b1) {
    asm volatile(
        "mma.sync.aligned.m16n8k16.row.col.f32.f16.f16.f32 "
        "{%0,%1,%2,%3}, {%4,%5,%6,%7}, {%8,%9}, {%0,%1,%2,%3};"
        : "+f"(c[0]), "+f"(c[1]), "+f"(c[2]), "+f"(c[3])
        : "r"(a[0]), "r"(a[1]), "r"(a[2]), "r"(a[3]), "r"(b0), "r"(b1));
}

// ---------------- kernel: fp16 mma GEMM + fused softmax moments + fused combine ----------------
// grid (NSTRIP, P), 512 threads / 16 warps.  (Round-10 structure.)
// Frags of 16 kp: warp w owns frag w; warps 8-15 also frag w+8; warp 0 also frag 24.
// Staging (warps 0-7 ONLY -> R[] dead in compute-heavy warps): thread owns column
// m = (w&7)*8+(lane&7), k-quarter kg = lane>>3; norms via intra-warp shfl.
// One __syncthreads per 64-col chunk. Last-arriving CTA combines (1 thread / keypoint).
__global__ void __launch_bounds__(NTHREADS, 1)
k_match(const float* __restrict__ dense, const float* __restrict__ kdesc,
        const float* __restrict__ kscores,
        const int* __restrict__ tgt_ids, const int* __restrict__ src_ids,
        float* __restrict__ out, int out_size) {
    extern __shared__ char sm[];
    const uint32_t sb = (uint32_t)__cvta_generic_to_shared(sm);
    const int tid = threadIdx.x, w = tid >> 5, lane = tid & 31;
    const int strip = blockIdx.x, p = blockIdx.y;
    const int P = gridDim.y;
    const int c0 = (strip * NCHUNK_G) / NSTRIP;
    const int c1 = ((strip + 1) * NCHUNK_G) / NSTRIP;
    const float* srcb = dense + (size_t)src_ids[p] * CDIM * HW_;

    const bool is_stage = (w < 8);
    const int mcol = (w & 7) * 8 + (lane & 7);   // column within chunk
    const int kg   = lane >> 3;                  // k-quarter (16 k values)

    // ---- early LDG of chunk c0 (staging warps) ----
    float R[16];
    if (is_stage) {
#pragma unroll
        for (int i = 0; i < 16; ++i)
            R[i] = srcb[(size_t)(kg * 16 + i) * HW_ + (size_t)c0 * CHUNK_M + mcol];
    }

    // ---- build A tile: normalize tgt inline, fold LOGIT_C, single fp16 ----
    if (tid < NKP) {
        const int kp = tid;
        const float* tb = kdesc + (size_t)tgt_ids[p] * CDIM * NKP + kp;
        float v[CDIM];
        float ss = 0.f;
#pragma unroll
        for (int c = 0; c < CDIM; ++c) { v[c] = tb[c * NKP]; ss = fmaf(v[c], v[c], ss); }
        float inv = LOGIT_C / fmaxf(sqrtf(ss), 1e-12f);
#pragma unroll
        for (int kb = 0; kb < CDIM; kb += 8) {
            uint32_t q[4];
#pragma unroll
            for (int j = 0; j < 4; ++j)
                q[j] = pkh2(v[kb + 2 * j] * inv, v[kb + 2 * j + 1] * inv);
            *(uint4*)(sm + SA + kp * 144 + kb * 2) = make_uint4(q[0], q[1], q[2], q[3]);
        }
    }

    // ---- prologue: convert chunk c0 (norm via shfl), prefetch c0+1 ----
    if (is_stage) {
        float ss = 0.f;
#pragma unroll
        for (int i = 0; i < 16; ++i) ss = fmaf(R[i], R[i], ss);
        ss += __shfl_xor_sync(0xffffffffu, ss, 8);
        ss += __shfl_xor_sync(0xffffffffu, ss, 16);
        float inv = 1.0f / fmaxf(sqrtf(ss), 1e-12f);
        char* bb = sm + SB + (c0 & 1) * 9216;
        uint32_t q[8];
#pragma unroll
        for (int j = 0; j < 8; ++j) q[j] = pkh2(R[2 * j] * inv, R[2 * j + 1] * inv);
        *(uint4*)(bb + mcol * 144 + kg * 32)      = make_uint4(q[0], q[1], q[2], q[3]);
        *(uint4*)(bb + mcol * 144 + kg * 32 + 16) = make_uint4(q[4], q[5], q[6], q[7]);
        if (c0 + 1 < c1) {
#pragma unroll
            for (int i = 0; i < 16; ++i)
                R[i] = srcb[(size_t)(kg * 16 + i) * HW_ + (size_t)(c0 + 1) * CHUNK_M + mcol];
        }
    }

    // frag assignment: slot 0 = frag w; slot 1 = w+8 (warps 8-15) or 24 (warp 0)
    const int f1 = (w >= 8) ? (w + 8) : (w == 0 ? 24 : -1);

    // persistent softmax moment accumulators [slot][rowpart]
    float S[2][2]  = {{0.f,0.f},{0.f,0.f}};
    float XO[2][2] = {{0.f,0.f},{0.f,0.f}};
    float XB[2][2] = {{0.f,0.f},{0.f,0.f}};
    float Yc[2][2] = {{0.f,0.f},{0.f,0.f}};

    const int preA = ((lane & 7) + ((lane >> 3) & 1) * 8) * 144 + ((lane >> 4) & 1) * 16;
    const int preB = ((lane & 7) + ((lane >> 4) & 1) * 8) * 144 + ((lane >> 3) & 1) * 16;
    const float xol = (float)((lane & 3) * 2);

    for (int t = c0; t < c1; ++t) {
        __syncthreads();   // buf[t&1] ready; prior chunk's readers of buf[(t+1)&1] done

        // ---- staging first: convert chunk t+1 into buf[(t+1)&1], prefetch t+2 ----
        if (is_stage && t + 1 < c1) {
            float ss = 0.f;
#pragma unroll
            for (int i = 0; i < 16; ++i) ss = fmaf(R[i], R[i], ss);
            ss += __shfl_xor_sync(0xffffffffu, ss, 8);
            ss += __shfl_xor_sync(0xffffffffu, ss, 16);
            float inv = 1.0f / fmaxf(sqrtf(ss), 1e-12f);
            char* bb = sm + SB + ((t + 1) & 1) * 9216;
            uint32_t q[8];
#pragma unroll
            for (int j = 0; j < 8; ++j) q[j] = pkh2(R[2 * j] * inv, R[2 * j + 1] * inv);
            *(uint4*)(bb + mcol * 144 + kg * 32)      = make_uint4(q[0], q[1], q[2], q[3]);
            *(uint4*)(bb + mcol * 144 + kg * 32 + 16) = make_uint4(q[4], q[5], q[6], q[7]);
            if (t + 2 < c1) {
#pragma unroll
                for (int i = 0; i < 16; ++i)
                    R[i] = srcb[(size_t)(kg * 16 + i) * HW_ + (size_t)(t + 2) * CHUNK_M + mcol];
            }
        }

        // ---- compute chunk t ----
        const uint32_t Bb = sb + SB + (t & 1) * 9216;
        const int m0 = t * CHUNK_M;
        const float xb = (float)(m0 & 255), yv = (float)(m0 >> 8);

#pragma unroll
        for (int slot = 0; slot < 2; ++slot) {
            const int f = (slot == 0) ? w : f1;
            if (f < 0) continue;
            const uint32_t Ah = sb + SA + f * 16 * 144 + preA;
            float c[8][4];
#pragma unroll
            for (int ff = 0; ff < 8; ++ff)      // fold -100*log2e into accumulator init
                c[ff][0] = c[ff][1] = c[ff][2] = c[ff][3] = -LOGIT_C;

#pragma unroll
            for (int ks = 0; ks < 4; ++ks) {
                uint32_t ah[4];
                ldsm4(ah[0], ah[1], ah[2], ah[3], Ah + ks * 32);
#pragma unroll
                for (int fp = 0; fp < 4; ++fp) {
                    uint32_t b0, b1, b2, b3;
                    ldsm4(b0, b1, b2, b3, Bb + fp * 2304 + preB + ks * 32);
                    mma16816(c[2 * fp],     ah, b0, b1);
                    mma16816(c[2 * fp + 1], ah, b2, b3);
                }
            }

            // ---- epilogue: w = 2^c; rows = keypoints (in-register moments) ----
            float s0 = S[slot][0], s1 = S[slot][1];
            float x0 = XO[slot][0], x1 = XO[slot][1];
            const float sn0 = s0, sn1 = s1;
#pragma unroll
            for (int ff = 0; ff < 8; ++ff) {
                float xo = xol + (float)(ff * 8);
                float w0 = ex2f(c[ff][0]);
                float w1 = ex2f(c[ff][1]);
                float w2 = ex2f(c[ff][2]);
                float w3 = ex2f(c[ff][3]);
                s0 += w0 + w1;
                x0 = fmaf(w0, xo, x0); x0 = fmaf(w1, xo + 1.f, x0);
                s1 += w2 + w3;
                x1 = fmaf(w2, xo, x1); x1 = fmaf(w3, xo + 1.f, x1);
            }
            S[slot][0] = s0; S[slot][1] = s1; XO[slot][0] = x0; XO[slot][1] = x1;
            XB[slot][0] = fmaf(xb, s0 - sn0, XB[slot][0]);
            XB[slot][1] = fmaf(xb, s1 - sn1, XB[slot][1]);
            Yc[slot][0] = fmaf(yv, s0 - sn0, Yc[slot][0]);
            Yc[slot][1] = fmaf(yv, s1 - sn1, Yc[slot][1]);
        }
    }

    // ---- reduce over the 4 col-lanes and store partials (strip-major layout) ----
#pragma unroll
    for (int slot = 0; slot < 2; ++slot) {
        const int f = (slot == 0) ? w : f1;
        if (f < 0) continue;
#pragma unroll
        for (int rp = 0; rp < 2; ++rp) {
            float s = S[slot][rp], x = XO[slot][rp] + XB[slot][rp], y = Yc[slot][rp];
            s += __shfl_xor_sync(0xffffffffu, s, 1);
            x += __shfl_xor_sync(0xffffffffu, x, 1);
            y += __shfl_xor_sync(0xffffffffu, y, 1);
            s += __shfl_xor_sync(0xffffffffu, s, 2);
            x += __shfl_xor_sync(0xffffffffu, x, 2);
            y += __shfl_xor_sync(0xffffffffu, y, 2);
            if ((lane & 3) == 0) {
                int kp = f * 16 + (lane >> 2) + 8 * rp;
                g_part4[((size_t)strip * P + p) * NKP + kp] = make_float4(s, x, y, 0.f);
            }
        }
    }

    // ---- last-arriver combine: one thread per keypoint, coalesced strip loop ----
    __threadfence();
    __shared__ unsigned is_last;
    __syncthreads();
    if (tid == 0) {
        unsigned total = gridDim.x * gridDim.y;
        unsigned old = atomicAdd(&g_ctr, 1u);
        is_last = (old == total - 1u) ? 1u : 0u;
    }
    __syncthreads();
    if (is_last) {
        __threadfence();   // all partial writes visible
        if (tid == 0) {
            int base = P * NKP * 3;
            for (int pp = 0; pp < P; ++pp) {
                if (base + pp < out_size)     out[base + pp]     = (float)tgt_ids[pp];
                if (base + P + pp < out_size) out[base + P + pp] = (float)src_ids[pp];
            }
        }
        const int tot = P * NKP;
        for (int g = tid; g < tot; g += NTHREADS) {
            float Sg = 0.f, Xg = 0.f, Yg = 0.f;
            const float4* bp = g_part4 + g;
#pragma unroll 4
            for (int s = 0; s < NSTRIP; ++s) {
                float4 v = bp[(size_t)s * tot];
                Sg += v.x; Xg += v.y; Yg += v.z;
            }
            if (g * 2 + 1 < out_size) {
                out[g * 2 + 0] = Xg / Sg;
                out[g * 2 + 1] = Yg / Sg;
            }
            int pp = g / NKP, kp = g - pp * NKP;
            int so = P * NKP * 2 + g;
            if (so < out_size) out[so] = kscores[tgt_ids[pp] * NKP + kp];
        }
        __syncthreads();
        if (tid == 0) atomicExch(&g_ctr, 0u);   // reset for next graph replay
    }
}

// ---------------- launch ----------------
extern "C" void kernel_launch(void* const* d_in, const int* in_sizes, int n_in,
                              void* d_out, int out_size) {
    const float* kscores = (const float*)d_in[0];
    const float* kdesc   = (const float*)d_in[1];
    const float* dense   = (const float*)d_in[2];
    const int*   tgt_ids = (const int*)d_in[3];
    const int*   src_ids = (const int*)d_in[4];
    int P = in_sizes[3];
    if (P > PMAX) P = PMAX;
    float* out = (float*)d_out;

    cudaFuncSetAttribute(k_match, cudaFuncAttributeMaxDynamicSharedMemorySize, SMEMSZ);
    k_match<<<dim3(NSTRIP, P), NTHREADS, SMEMSZ>>>(dense, kdesc, kscores,
                                                   tgt_ids, src_ids, out, out_size);
}

// round 16
// speedup vs baseline: 1.7821x; 1.2479x over previous
#include <cuda_runtime.h>
#include <cuda_fp16.h>
#include <cstdint>

// ---------------- problem constants ----------------
#define HW_      65536
#define CDIM     64
#define NKP      400        // = 25 frags x 16, exact
#define PMAX     2
#define NSTRIP   74         // x P=2 -> 148 CTAs = one full wave
#define NCHUNK_G 1024       // 65536 / 64
#define CHUNK_M  64
#define NTHREADS 512        // 16 warps
#define LOGIT_C  144.26950408889634f   // 100 * log2(e)

// smem: A rows 144B stride (128B fp16 data + 16B pad); B bufs 64 rows x 144B
#define SA     0
#define SB     57600        // 2 bufs x 9216
#define SMEMSZ 76032

// ---------------- device scratch ----------------
__device__ float4 g_part4[PMAX * NKP * NSTRIP]; // (S, X, Y, _) per kp per strip

// ---------------- helpers ----------------
__device__ __forceinline__ float ex2f(float x) {
    float y; asm("ex2.approx.ftz.f32 %0, %1;" : "=f"(y) : "f"(x)); return y;
}
__device__ __forceinline__ uint32_t pkh2(float a, float b) {
    __half2 h = __floats2half2_rn(a, b);
    return *reinterpret_cast<uint32_t*>(&h);
}
__device__ __forceinline__ void ldsm4(uint32_t& r0, uint32_t& r1, uint32_t& r2, uint32_t& r3,
                                      uint32_t addr) {
    asm volatile("ldmatrix.sync.aligned.m8n8.x4.shared.b16 {%0,%1,%2,%3}, [%4];"
                 : "=r"(r0), "=r"(r1), "=r"(r2), "=r"(r3) : "r"(addr));
}
__device__ __forceinline__ void mma16816(float* c, const uint32_t* a, uint32_t b0, uint32_t b1) {
    asm volatile(
        "mma.sync.aligned.m16n8k16.row.col.f32.f16.f16.f32 "
        "{%0,%1,%2,%3}, {%4,%5,%6,%7}, {%8,%9}, {%0,%1,%2,%3};"
        : "+f"(c[0]), "+f"(c[1]), "+f"(c[2]), "+f"(c[3])
        : "r"(a[0]), "r"(a[1]), "r"(a[2]), "r"(a[3]), "r"(b0), "r"(b1));
}

// per-frag softmax-moment epilogue: w = 2^c (shift pre-folded); rows = keypoints
__device__ __forceinline__ void epi8(const float (*c)[4], float xol, float xb, float yv,
                                     float* S, float* XO, float* XB, float* Yc) {
    float s0 = S[0], s1 = S[1];
    float x0 = XO[0], x1 = XO[1];
    const float sn0 = s0, sn1 = s1;
#pragma unroll
    for (int ff = 0; ff < 8; ++ff) {
        float xo = xol + (float)(ff * 8);
        float w0 = ex2f(c[ff][0]);
        float w1 = ex2f(c[ff][1]);
        float w2 = ex2f(c[ff][2]);
        float w3 = ex2f(c[ff][3]);
        s0 += w0 + w1;
        x0 = fmaf(w0, xo, x0); x0 = fmaf(w1, xo + 1.f, x0);
        s1 += w2 + w3;
        x1 = fmaf(w2, xo, x1); x1 = fmaf(w3, xo + 1.f, x1);
    }
    S[0] = s0; S[1] = s1; XO[0] = x0; XO[1] = x1;
    XB[0] = fmaf(xb, s0 - sn0, XB[0]);
    XB[1] = fmaf(xb, s1 - sn1, XB[1]);
    Yc[0] = fmaf(yv, s0 - sn0, Yc[0]);
    Yc[1] = fmaf(yv, s1 - sn1, Yc[1]);
}

// ---------------- kernel 1: fp16 mma GEMM + fused softmax moments ----------------
// grid (NSTRIP, P), 512 threads / 16 warps.  (Round-10 structure.)
// Frags of 16 kp: warp w owns frag w; warps 8-15 also frag w+8; warp 0 also frag 24.
// Dual-frag warps load each B fragment ONCE and feed both frags (halves B LDSM traffic).
// Staging (warps 0-7 only): thread owns column m=(w&7)*8+(lane&7), k-quarter kg=lane>>3;
// norms via intra-warp shfl. One __syncthreads per 64-col chunk.
__global__ void __launch_bounds__(NTHREADS, 1)
k_match(const float* __restrict__ dense, const float* __restrict__ kdesc,
        const int* __restrict__ tgt_ids, const int* __restrict__ src_ids) {
    extern __shared__ char sm[];
    const uint32_t sb = (uint32_t)__cvta_generic_to_shared(sm);
    const int tid = threadIdx.x, w = tid >> 5, lane = tid & 31;
    const int strip = blockIdx.x, p = blockIdx.y;
    const int c0i = (strip * NCHUNK_G) / NSTRIP;
    const int c1i = ((strip + 1) * NCHUNK_G) / NSTRIP;
    const float* srcb = dense + (size_t)src_ids[p] * CDIM * HW_;

    const bool is_stage = (w < 8);
    const int mcol = (w & 7) * 8 + (lane & 7);
    const int kg   = lane >> 3;

    // ---- early LDG of chunk c0 (staging warps) ----
    float R[16];
    if (is_stage) {
#pragma unroll
        for (int i = 0; i < 16; ++i)
            R[i] = srcb[(size_t)(kg * 16 + i) * HW_ + (size_t)c0i * CHUNK_M + mcol];
    }

    // ---- build A tile: normalize tgt inline, fold LOGIT_C, single fp16 ----
    if (tid < NKP) {
        const int kp = tid;
        const float* tb = kdesc + (size_t)tgt_ids[p] * CDIM * NKP + kp;
        float v[CDIM];
        float ss = 0.f;
#pragma unroll
        for (int c = 0; c < CDIM; ++c) { v[c] = tb[c * NKP]; ss = fmaf(v[c], v[c], ss); }
        float inv = LOGIT_C / fmaxf(sqrtf(ss), 1e-12f);
#pragma unroll
        for (int kb = 0; kb < CDIM; kb += 8) {
            uint32_t q[4];
#pragma unroll
            for (int j = 0; j < 4; ++j)
                q[j] = pkh2(v[kb + 2 * j] * inv, v[kb + 2 * j + 1] * inv);
            *(uint4*)(sm + SA + kp * 144 + kb * 2) = make_uint4(q[0], q[1], q[2], q[3]);
        }
    }

    // ---- prologue: convert chunk c0 (norm via shfl), prefetch c0+1 ----
    if (is_stage) {
        float ss = 0.f;
#pragma unroll
        for (int i = 0; i < 16; ++i) ss = fmaf(R[i], R[i], ss);
        ss += __shfl_xor_sync(0xffffffffu, ss, 8);
        ss += __shfl_xor_sync(0xffffffffu, ss, 16);
        float inv = 1.0f / fmaxf(sqrtf(ss), 1e-12f);
        char* bb = sm + SB + (c0i & 1) * 9216;
        uint32_t q[8];
#pragma unroll
        for (int j = 0; j < 8; ++j) q[j] = pkh2(R[2 * j] * inv, R[2 * j + 1] * inv);
        *(uint4*)(bb + mcol * 144 + kg * 32)      = make_uint4(q[0], q[1], q[2], q[3]);
        *(uint4*)(bb + mcol * 144 + kg * 32 + 16) = make_uint4(q[4], q[5], q[6], q[7]);
        if (c0i + 1 < c1i) {
#pragma unroll
            for (int i = 0; i < 16; ++i)
                R[i] = srcb[(size_t)(kg * 16 + i) * HW_ + (size_t)(c0i + 1) * CHUNK_M + mcol];
        }
    }

    // frag assignment: slot 0 = frag w; slot 1 = w+8 (warps 8-15) or 24 (warp 0)
    const int f1 = (w >= 8) ? (w + 8) : (w == 0 ? 24 : -1);

    float S[2][2]  = {{0.f,0.f},{0.f,0.f}};
    float XO[2][2] = {{0.f,0.f},{0.f,0.f}};
    float XB[2][2] = {{0.f,0.f},{0.f,0.f}};
    float Yc[2][2] = {{0.f,0.f},{0.f,0.f}};

    const int preA = ((lane & 7) + ((lane >> 3) & 1) * 8) * 144 + ((lane >> 4) & 1) * 16;
    const int preB = ((lane & 7) + ((lane >> 4) & 1) * 8) * 144 + ((lane >> 3) & 1) * 16;
    const float xol = (float)((lane & 3) * 2);
    const uint32_t Ah0 = sb + SA + w * 16 * 144 + preA;
    const uint32_t Ah1 = sb + SA + ((f1 < 0 ? 0 : f1) * 16) * 144 + preA;

    for (int t = c0i; t < c1i; ++t) {
        __syncthreads();   // buf[t&1] ready; prior chunk's readers of buf[(t+1)&1] done

        // ---- staging first: convert chunk t+1 into buf[(t+1)&1], prefetch t+2 ----
        if (is_stage && t + 1 < c1i) {
            float ss = 0.f;
#pragma unroll
            for (int i = 0; i < 16; ++i) ss = fmaf(R[i], R[i], ss);
            ss += __shfl_xor_sync(0xffffffffu, ss, 8);
            ss += __shfl_xor_sync(0xffffffffu, ss, 16);
            float inv = 1.0f / fmaxf(sqrtf(ss), 1e-12f);
            char* bb = sm + SB + ((t + 1) & 1) * 9216;
            uint32_t q[8];
#pragma unroll
            for (int j = 0; j < 8; ++j) q[j] = pkh2(R[2 * j] * inv, R[2 * j + 1] * inv);
            *(uint4*)(bb + mcol * 144 + kg * 32)      = make_uint4(q[0], q[1], q[2], q[3]);
            *(uint4*)(bb + mcol * 144 + kg * 32 + 16) = make_uint4(q[4], q[5], q[6], q[7]);
            if (t + 2 < c1i) {
#pragma unroll
                for (int i = 0; i < 16; ++i)
                    R[i] = srcb[(size_t)(kg * 16 + i) * HW_ + (size_t)(t + 2) * CHUNK_M + mcol];
            }
        }

        // ---- compute chunk t ----
        const uint32_t Bb = sb + SB + (t & 1) * 9216;
        const int m0 = t * CHUNK_M;
        const float xb = (float)(m0 & 255), yv = (float)(m0 >> 8);

        float c0[8][4];
#pragma unroll
        for (int ff = 0; ff < 8; ++ff)
            c0[ff][0] = c0[ff][1] = c0[ff][2] = c0[ff][3] = -LOGIT_C;

        if (f1 >= 0) {
            // dual-frag path: B fragments loaded once, used by both frags
            float c1[8][4];
#pragma unroll
            for (int ff = 0; ff < 8; ++ff)
                c1[ff][0] = c1[ff][1] = c1[ff][2] = c1[ff][3] = -LOGIT_C;
#pragma unroll
            for (int ks = 0; ks < 4; ++ks) {
                uint32_t a0[4], a1[4];
                ldsm4(a0[0], a0[1], a0[2], a0[3], Ah0 + ks * 32);
                ldsm4(a1[0], a1[1], a1[2], a1[3], Ah1 + ks * 32);
#pragma unroll
                for (int fp = 0; fp < 4; ++fp) {
                    uint32_t b0, b1, b2, b3;
                    ldsm4(b0, b1, b2, b3, Bb + fp * 2304 + preB + ks * 32);
                    mma16816(c0[2 * fp],     a0, b0, b1);
                    mma16816(c0[2 * fp + 1], a0, b2, b3);
                    mma16816(c1[2 * fp],     a1, b0, b1);
                    mma16816(c1[2 * fp + 1], a1, b2, b3);
                }
            }
            epi8(c0, xol, xb, yv, S[0], XO[0], XB[0], Yc[0]);
            epi8(c1, xol, xb, yv, S[1], XO[1], XB[1], Yc[1]);
        } else {
            // single-frag path
#pragma unroll
            for (int ks = 0; ks < 4; ++ks) {
                uint32_t a0[4];
                ldsm4(a0[0], a0[1], a0[2], a0[3], Ah0 + ks * 32);
#pragma unroll
                for (int fp = 0; fp < 4; ++fp) {
                    uint32_t b0, b1, b2, b3;
                    ldsm4(b0, b1, b2, b3, Bb + fp * 2304 + preB + ks * 32);
                    mma16816(c0[2 * fp],     a0, b0, b1);
                    mma16816(c0[2 * fp + 1], a0, b2, b3);
                }
            }
            epi8(c0, xol, xb, yv, S[0], XO[0], XB[0], Yc[0]);
        }
    }

    // ---- reduce over the 4 col-lanes and store partials ----
#pragma unroll
    for (int slot = 0; slot < 2; ++slot) {
        const int f = (slot == 0) ? w : f1;
        if (f < 0) continue;
#pragma unroll
        for (int rp = 0; rp < 2; ++rp) {
            float s = S[slot][rp], x = XO[slot][rp] + XB[slot][rp], y = Yc[slot][rp];
            s += __shfl_xor_sync(0xffffffffu, s, 1);
            x += __shfl_xor_sync(0xffffffffu, x, 1);
            y += __shfl_xor_sync(0xffffffffu, y, 1);
            s += __shfl_xor_sync(0xffffffffu, s, 2);
            x += __shfl_xor_sync(0xffffffffu, x, 2);
            y += __shfl_xor_sync(0xffffffffu, y, 2);
            if ((lane & 3) == 0) {
                int kp = f * 16 + (lane >> 2) + 8 * rp;
                g_part4[((size_t)p * NKP + kp) * NSTRIP + strip] = make_float4(s, x, y, 0.f);
            }
        }
    }
}

// ---------------- kernel 2: combine partials + emit scores/ids (4 kp / 128-thr block) ----------------
__global__ void k_combine(const float* __restrict__ kscores,
                          const int* __restrict__ tgt_ids, const int* __restrict__ src_ids,
                          float* __restrict__ out, int P, int out_size) {
    int gw   = blockIdx.x * 4 + (threadIdx.x >> 5);
    int lane = threadIdx.x & 31;
    if (blockIdx.x == 0 && threadIdx.x == 0) {
        int base = P * NKP * 3;
        for (int pp = 0; pp < P; ++pp) {
            if (base + pp < out_size)     out[base + pp]     = (float)tgt_ids[pp];
            if (base + P + pp < out_size) out[base + P + pp] = (float)src_ids[pp];
        }
    }
    if (gw >= P * NKP) return;
    int p = gw / NKP, kp = gw - p * NKP;
    const float4* base = &g_part4[((size_t)p * NKP + kp) * NSTRIP];
    float4 v0 = base[lane];
    float4 v1 = base[lane + 32];
    float4 v2 = (lane + 64 < NSTRIP) ? base[lane + 64] : make_float4(0.f, 0.f, 0.f, 0.f);
    float S = v0.x + v1.x + v2.x;
    float X = v0.y + v1.y + v2.y;
    float Y = v0.z + v1.z + v2.z;
#pragma unroll
    for (int off = 16; off; off >>= 1) {
        S += __shfl_xor_sync(0xffffffffu, S, off);
        X += __shfl_xor_sync(0xffffffffu, X, off);
        Y += __shfl_xor_sync(0xffffffffu, Y, off);
    }
    if (lane == 0) {
        if (gw * 2 + 1 < out_size) {
            out[gw * 2 + 0] = X / S;
            out[gw * 2 + 1] = Y / S;
        }
        int so = P * NKP * 2 + p * NKP + kp;
        if (so < out_size) out[so] = kscores[tgt_ids[p] * NKP + kp];
    }
}

// ---------------- launch ----------------
extern "C" void kernel_launch(void* const* d_in, const int* in_sizes, int n_in,
                              void* d_out, int out_size) {
    const float* kscores = (const float*)d_in[0];
    const float* kdesc   = (const float*)d_in[1];
    const float* dense   = (const float*)d_in[2];
    const int*   tgt_ids = (const int*)d_in[3];
    const int*   src_ids = (const int*)d_in[4];
    int P = in_sizes[3];
    if (P > PMAX) P = PMAX;
    float* out = (float*)d_out;

    cudaFuncSetAttribute(k_match, cudaFuncAttributeMaxDynamicSharedMemorySize, SMEMSZ);
    k_match<<<dim3(NSTRIP, P), NTHREADS, SMEMSZ>>>(dense, kdesc, tgt_ids, src_ids);

    k_combine<<<(P * NKP + 3) / 4, 128>>>(kscores, tgt_ids, src_ids, out, P, out_size);
}